// round 3
// baseline (speedup 1.0000x reference)
#include <cuda_runtime.h>
#include <cuda_bf16.h>
#include <cstdint>

#define NN 100000
#define F1 64
#define F2 16

typedef unsigned long long ull;

// Scratch (allocation-free rule: __device__ globals)
__device__ float g_deg[NN];
__device__ float g_acc1[NN * F1];
__device__ float g_h1[NN * F1];
__device__ float g_z2[NN * F2];
__device__ float g_acc2[NN * F2];

// ---------------- f32x2 packed helpers (sm_100+) ----------------
__device__ __forceinline__ ull pack2(float v) {
    ull r;
    asm("mov.b64 %0, {%1, %1};" : "=l"(r) : "f"(v));
    return r;
}
__device__ __forceinline__ ull fma2(ull a, ull b, ull c) {
    ull d;
    asm("fma.rn.f32x2 %0, %1, %2, %3;" : "=l"(d) : "l"(a), "l"(b), "l"(c));
    return d;
}
__device__ __forceinline__ float2 unpack2(ull v) {
    float2 f;
    asm("mov.b64 {%0, %1}, %2;" : "=f"(f.x), "=f"(f.y) : "l"(v));
    return f;
}

// ---------------- zero scratch (acc1 + deg; acc2 zeroed in combine2) ----------------
__global__ void k_zero() {
    int i = blockIdx.x * blockDim.x + threadIdx.x;
    if (i < NN * F1) g_acc1[i] = 0.f;
    if (i < NN)      g_deg[i]  = 0.f;
}

// ---------------- layer-1 scatter + degree: acc1[dst] += x[src] ----------------
__global__ void k_scatter64(const float* __restrict__ x,
                            const int* __restrict__ src,
                            const int* __restrict__ dst, int E) {
    int t = blockIdx.x * blockDim.x + threadIdx.x;
    int e = t >> 4;
    int c = (t & 15) << 2;  // feature chunk (4 floats)
    if (e >= E) return;
    int s = src[e], d = dst[e];
    float4 v = *reinterpret_cast<const float4*>(x + (size_t)s * F1 + c);
    float* p = g_acc1 + (size_t)d * F1 + c;
    asm volatile("red.global.add.v4.f32 [%0], {%1,%2,%3,%4};"
                 :: "l"(p), "f"(v.x), "f"(v.y), "f"(v.z), "f"(v.w) : "memory");
    if ((t & 15) == 0) atomicAdd(&g_deg[d], 1.0f);
}

// ---------------- layer-1 combine: h1 = relu(x@Ws + (acc1/deg)@Wn + b) ----------------
// 128 nodes/block, 256 threads. Thread: cg = tid&7 (8 output cols), ng = tid>>3
// (nodes ng, ng+32, ng+64, ng+96). C=8 x Nd=4 tile -> LDS/MAC = 0.094.
// sX/sA rows padded to 68 floats so the 4 per-warp node addresses hit 4 banks.
#define P1 68
__global__ void __launch_bounds__(256) k_combine1(
    const float* __restrict__ x,
    const float* __restrict__ Ws, const float* __restrict__ Wn,
    const float* __restrict__ b) {
    extern __shared__ float s[];
    float* sWs   = s;           // 64*64
    float* sWn   = s + 4096;    // 64*64
    float* sX    = s + 8192;    // 128*P1
    float* sA    = s + 8192 + 128 * P1;
    float* sDinv = s + 8192 + 256 * P1;        // 128
    float* sB    = s + 8192 + 256 * P1 + 128;  // 64

    int tid   = threadIdx.x;
    int node0 = blockIdx.x * 128;

    for (int i = tid; i < 1024; i += 256) {
        reinterpret_cast<float4*>(sWs)[i] = reinterpret_cast<const float4*>(Ws)[i];
        reinterpret_cast<float4*>(sWn)[i] = reinterpret_cast<const float4*>(Wn)[i];
    }
    if (tid < 64) sB[tid] = b[tid];
    if (tid < 128) {
        int n = node0 + tid;
        float d = (n < NN) ? g_deg[n] : 1.f;
        sDinv[tid] = 1.0f / fmaxf(d, 1.0f);
    }
    for (int i = tid; i < 128 * 16; i += 256) {
        int row = i >> 4, c = i & 15;
        int n = node0 + row;
        float4 vx = make_float4(0.f, 0.f, 0.f, 0.f), va = vx;
        if (n < NN) {
            vx = reinterpret_cast<const float4*>(x + (size_t)n * F1)[c];
            va = reinterpret_cast<const float4*>(g_acc1 + (size_t)n * F1)[c];
        }
        *reinterpret_cast<float4*>(sX + row * P1 + 4 * c) = vx;
        *reinterpret_cast<float4*>(sA + row * P1 + 4 * c) = va;
    }
    __syncthreads();

    int j8 = (tid & 7) << 3;
    int ng = tid >> 3;  // 0..31
    int rb[4] = { ng * P1, (ng + 32) * P1, (ng + 64) * P1, (ng + 96) * P1 };

    ull as_[4][4], an_[4][4];
#pragma unroll
    for (int nn = 0; nn < 4; ++nn)
#pragma unroll
        for (int p = 0; p < 4; ++p) { as_[nn][p] = 0ull; an_[nn][p] = 0ull; }

#pragma unroll 2
    for (int k = 0; k < 64; ++k) {
        const float* wp = sWs + k * 64 + j8;
        const float* wq = sWn + k * 64 + j8;
        ulonglong2 wsA = *reinterpret_cast<const ulonglong2*>(wp);
        ulonglong2 wsB = *reinterpret_cast<const ulonglong2*>(wp + 4);
        ulonglong2 wnA = *reinterpret_cast<const ulonglong2*>(wq);
        ulonglong2 wnB = *reinterpret_cast<const ulonglong2*>(wq + 4);
#pragma unroll
        for (int nn = 0; nn < 4; ++nn) {
            ull xx = pack2(sX[rb[nn] + k]);
            ull aa = pack2(sA[rb[nn] + k]);
            as_[nn][0] = fma2(xx, wsA.x, as_[nn][0]);
            as_[nn][1] = fma2(xx, wsA.y, as_[nn][1]);
            as_[nn][2] = fma2(xx, wsB.x, as_[nn][2]);
            as_[nn][3] = fma2(xx, wsB.y, as_[nn][3]);
            an_[nn][0] = fma2(aa, wnA.x, an_[nn][0]);
            an_[nn][1] = fma2(aa, wnA.y, an_[nn][1]);
            an_[nn][2] = fma2(aa, wnB.x, an_[nn][2]);
            an_[nn][3] = fma2(aa, wnB.y, an_[nn][3]);
        }
    }

    float4 bl = *reinterpret_cast<const float4*>(sB + j8);
    float4 bh = *reinterpret_cast<const float4*>(sB + j8 + 4);
#pragma unroll
    for (int nn = 0; nn < 4; ++nn) {
        int n  = ng + nn * 32;
        int gn = node0 + n;
        if (gn < NN) {
            ull dd = pack2(sDinv[n]);
            float2 r0 = unpack2(fma2(an_[nn][0], dd, as_[nn][0]));
            float2 r1 = unpack2(fma2(an_[nn][1], dd, as_[nn][1]));
            float2 r2 = unpack2(fma2(an_[nn][2], dd, as_[nn][2]));
            float2 r3 = unpack2(fma2(an_[nn][3], dd, as_[nn][3]));
            float4 o0, o1;
            o0.x = fmaxf(r0.x + bl.x, 0.f); o0.y = fmaxf(r0.y + bl.y, 0.f);
            o0.z = fmaxf(r1.x + bl.z, 0.f); o0.w = fmaxf(r1.y + bl.w, 0.f);
            o1.x = fmaxf(r2.x + bh.x, 0.f); o1.y = fmaxf(r2.y + bh.y, 0.f);
            o1.z = fmaxf(r3.x + bh.z, 0.f); o1.w = fmaxf(r3.y + bh.w, 0.f);
            *reinterpret_cast<float4*>(g_h1 + (size_t)gn * F1 + j8)     = o0;
            *reinterpret_cast<float4*>(g_h1 + (size_t)gn * F1 + j8 + 4) = o1;
        }
    }
}

// ---------------- layer-2 combine: fused GEMM [NN x 64] @ [64 x 32] ----------------
// Cols 0..15 -> out (self + bias), cols 16..31 -> z2 (pre-aggregation neigh term).
// 256 nodes/block, 256 threads: cg = tid&3 (8 cols), ng = tid>>2 (nodes ng+64*nn).
// Also zeroes acc2. sH rows padded to 68.
#define P2 68
__global__ void __launch_bounds__(256) k_combine2(
    const float* __restrict__ Ws, const float* __restrict__ Wn,
    const float* __restrict__ b, float* __restrict__ out) {
    extern __shared__ float s[];
    float* sW = s;         // 64 x 32 : [k][0:16]=Ws[k], [k][16:32]=Wn[k]
    float* sH = s + 2048;  // 256 x P2
    float* sB = s + 2048 + 256 * P2;  // 16

    int tid   = threadIdx.x;
    int node0 = blockIdx.x * 256;

    {
        int k = tid >> 2, c = tid & 3;  // 256 threads cover 64 k x 4 chunks
        reinterpret_cast<float4*>(sW + k * 32)[c]      = reinterpret_cast<const float4*>(Ws + k * 16)[c];
        reinterpret_cast<float4*>(sW + k * 32 + 16)[c] = reinterpret_cast<const float4*>(Wn + k * 16)[c];
    }
    if (tid < 16) sB[tid] = b[tid];
    for (int i = tid; i < 256 * 16; i += 256) {
        int row = i >> 4, c = i & 15;
        int n = node0 + row;
        float4 v = make_float4(0.f, 0.f, 0.f, 0.f);
        if (n < NN) v = reinterpret_cast<const float4*>(g_h1 + (size_t)n * F1)[c];
        *reinterpret_cast<float4*>(sH + row * P2 + 4 * c) = v;
    }
    __syncthreads();

    int j8 = (tid & 3) << 3;  // 0,8,16,24
    int ng = tid >> 2;        // 0..63
    int rb[4] = { ng * P2, (ng + 64) * P2, (ng + 128) * P2, (ng + 192) * P2 };

    ull ac[4][4];
#pragma unroll
    for (int nn = 0; nn < 4; ++nn)
#pragma unroll
        for (int p = 0; p < 4; ++p) ac[nn][p] = 0ull;

#pragma unroll 2
    for (int k = 0; k < 64; ++k) {
        const float* wp = sW + k * 32 + j8;
        ulonglong2 wA = *reinterpret_cast<const ulonglong2*>(wp);
        ulonglong2 wB = *reinterpret_cast<const ulonglong2*>(wp + 4);
#pragma unroll
        for (int nn = 0; nn < 4; ++nn) {
            ull hh = pack2(sH[rb[nn] + k]);
            ac[nn][0] = fma2(hh, wA.x, ac[nn][0]);
            ac[nn][1] = fma2(hh, wA.y, ac[nn][1]);
            ac[nn][2] = fma2(hh, wB.x, ac[nn][2]);
            ac[nn][3] = fma2(hh, wB.y, ac[nn][3]);
        }
    }

    if (j8 < 16) {  // self matrix -> out (+bias)
        float4 bl = *reinterpret_cast<const float4*>(sB + j8);
        float4 bh = *reinterpret_cast<const float4*>(sB + j8 + 4);
#pragma unroll
        for (int nn = 0; nn < 4; ++nn) {
            int gn = node0 + ng + nn * 64;
            if (gn < NN) {
                float2 r0 = unpack2(ac[nn][0]), r1 = unpack2(ac[nn][1]);
                float2 r2 = unpack2(ac[nn][2]), r3 = unpack2(ac[nn][3]);
                float4 o0 = make_float4(r0.x + bl.x, r0.y + bl.y, r1.x + bl.z, r1.y + bl.w);
                float4 o1 = make_float4(r2.x + bh.x, r2.y + bh.y, r3.x + bh.z, r3.y + bh.w);
                *reinterpret_cast<float4*>(out + (size_t)gn * F2 + j8)     = o0;
                *reinterpret_cast<float4*>(out + (size_t)gn * F2 + j8 + 4) = o1;
            }
        }
    } else {  // neigh matrix -> z2; also zero acc2
        int j = j8 - 16;
        float4 z = make_float4(0.f, 0.f, 0.f, 0.f);
#pragma unroll
        for (int nn = 0; nn < 4; ++nn) {
            int gn = node0 + ng + nn * 64;
            if (gn < NN) {
                float2 r0 = unpack2(ac[nn][0]), r1 = unpack2(ac[nn][1]);
                float2 r2 = unpack2(ac[nn][2]), r3 = unpack2(ac[nn][3]);
                float4 o0 = make_float4(r0.x, r0.y, r1.x, r1.y);
                float4 o1 = make_float4(r2.x, r2.y, r3.x, r3.y);
                *reinterpret_cast<float4*>(g_z2 + (size_t)gn * F2 + j)     = o0;
                *reinterpret_cast<float4*>(g_z2 + (size_t)gn * F2 + j + 4) = o1;
                *reinterpret_cast<float4*>(g_acc2 + (size_t)gn * F2 + j)     = z;
                *reinterpret_cast<float4*>(g_acc2 + (size_t)gn * F2 + j + 4) = z;
            }
        }
    }
}

// ---------------- layer-2 scatter: acc2[dst] += z2[src], width 16 ----------------
__global__ void k_scatter16(const int* __restrict__ src,
                            const int* __restrict__ dst, int E) {
    int t = blockIdx.x * blockDim.x + threadIdx.x;
    int e = t >> 2;
    int c = (t & 3) << 2;
    if (e >= E) return;
    int s = src[e], d = dst[e];
    float4 v = *reinterpret_cast<const float4*>(g_z2 + (size_t)s * F2 + c);
    float* p = g_acc2 + (size_t)d * F2 + c;
    asm volatile("red.global.add.v4.f32 [%0], {%1,%2,%3,%4};"
                 :: "l"(p), "f"(v.x), "f"(v.y), "f"(v.z), "f"(v.w) : "memory");
}

// ---------------- finalize: out += acc2 / deg ----------------
__global__ void k_final(float* __restrict__ out) {
    int i = blockIdx.x * blockDim.x + threadIdx.x;  // one float4 per thread
    if (i >= NN * F2 / 4) return;
    int n = i >> 2;
    float dinv = 1.0f / fmaxf(g_deg[n], 1.0f);
    float4 o = reinterpret_cast<float4*>(out)[i];
    float4 a = reinterpret_cast<const float4*>(g_acc2)[i];
    o.x = fmaf(a.x, dinv, o.x); o.y = fmaf(a.y, dinv, o.y);
    o.z = fmaf(a.z, dinv, o.z); o.w = fmaf(a.w, dinv, o.w);
    reinterpret_cast<float4*>(out)[i] = o;
}

extern "C" void kernel_launch(void* const* d_in, const int* in_sizes, int n_in,
                              void* d_out, int out_size) {
    const float* x   = (const float*)d_in[0];
    const int*   src = (const int*)d_in[1];
    const int*   dst = (const int*)d_in[2];
    const float* W1s = (const float*)d_in[3];
    const float* W1n = (const float*)d_in[4];
    const float* b1  = (const float*)d_in[5];
    const float* W2s = (const float*)d_in[6];
    const float* W2n = (const float*)d_in[7];
    const float* b2  = (const float*)d_in[8];
    float* out = (float*)d_out;
    int E = in_sizes[1];

    const int smem1 = (8192 + 256 * P1 + 128 + 64) * sizeof(float);
    const int smem2 = (2048 + 256 * P2 + 16) * sizeof(float);
    static bool attr_done = false;  // host-side config only
    if (!attr_done) {
        cudaFuncSetAttribute(k_combine1, cudaFuncAttributeMaxDynamicSharedMemorySize, smem1);
        cudaFuncSetAttribute(k_combine2, cudaFuncAttributeMaxDynamicSharedMemorySize, smem2);
        attr_done = true;
    }

    int nblk;

    nblk = (NN * F1 + 255) / 256;
    k_zero<<<nblk, 256>>>();

    nblk = (E * 16 + 255) / 256;
    k_scatter64<<<nblk, 256>>>(x, src, dst, E);

    nblk = (NN + 127) / 128;
    k_combine1<<<nblk, 256, smem1>>>(x, W1s, W1n, b1);

    nblk = (NN + 255) / 256;
    k_combine2<<<nblk, 256, smem2>>>(W2s, W2n, b2, out);

    nblk = (E * 4 + 255) / 256;
    k_scatter16<<<nblk, 256>>>(src, dst, E);

    nblk = (NN * F2 / 4 + 255) / 256;
    k_final<<<nblk, 256>>>(out);
}